// round 11
// baseline (speedup 1.0000x reference)
#include <cuda_runtime.h>

// Dempster-Shafer evidential layer.
// Prepped uniform operands live in a __device__ global buffer, read with
// uniform-address LDG.128 (1 L1 wavefront/warp broadcast) — no __constant__
// bank, no memcpy graph node. k-pairs in f32x2 lanes; 2 points/thread;
// K split into 2 halves of 10 prototypes to bound live registers.
//
// s_k = 2^( hgn_k*||x||^2 + <x, sc_k*W_k> + c2_k ),  sc_k = gamma_k^2*log2e,
// hgn_k = -0.5*sc_k,  c2_k = hgn_k*||W_k||^2 + log2(alphap_k)
// Q_m = prod_k (U[k][m]*s_k + (1-s_k)),  O = prod_k (1-s_k)
// out = normalize([Q_m - O, O])

#define CC   16
#define KK   20
#define MM   4
#define HWD  (64*64*64)
#define PWD  (HWD/2)           // 131072 point-pairs per volume
#define NTHR (2*PWD)           // 262144 threads
#define BLK  128

typedef unsigned long long u64;

__device__ __forceinline__ u64 fma2(u64 a, u64 b, u64 c) {
    u64 d; asm("fma.rn.f32x2 %0, %1, %2, %3;" : "=l"(d) : "l"(a), "l"(b), "l"(c)); return d;
}
__device__ __forceinline__ u64 mul2(u64 a, u64 b) {
    u64 d; asm("mul.rn.f32x2 %0, %1, %2;" : "=l"(d) : "l"(a), "l"(b)); return d;
}
__device__ __forceinline__ u64 add2(u64 a, u64 b) {
    u64 d; asm("add.rn.f32x2 %0, %1, %2;" : "=l"(d) : "l"(a), "l"(b)); return d;
}
__device__ __forceinline__ u64 pk(float lo, float hi) {
    u64 r; asm("mov.b64 %0, {%1,%2};" : "=l"(r) : "f"(lo), "f"(hi)); return r;
}
__device__ __forceinline__ void upk(u64 v, float& lo, float& hi) {
    asm("mov.b64 {%0,%1}, %2;" : "=f"(lo), "=f"(hi) : "l"(v));
}
__device__ __forceinline__ float ex2f(float x) {
    float r; asm("ex2.approx.f32 %0, %1;" : "=f"(r) : "f"(x)); return r;
}
__device__ __forceinline__ float rcpf(float x) {
    float r; asm("rcp.approx.f32 %0, %1;" : "=f"(r) : "f"(x)); return r;
}
__device__ __forceinline__ ulonglong2 ldu2(const ulonglong2* p) {
    ulonglong2 r;
    asm("ld.global.nc.v2.u64 {%0,%1}, [%2];" : "=l"(r.x), "=l"(r.y) : "l"(p));
    return r;
}

#define ONEp  0x3F8000003F800000ull
#define NEG1p 0xBF800000BF800000ull
#define L2E   1.4426950408889634f

// Layout (ulonglong2 units):
//  [0..95]   weights: (half,c) -> 3 vecs: {(w01),(w23)} {(w45),(w67)} {(w89),pad}
//            wAB = pk(sc[kb+A]*W[kb+A][c], sc[kb+B]*W[kb+B][c]), kb = half*10
//  [96..125] epilogue: kpair jp -> 3 vecs: {(hgnP),(c2P)} {(u0P),(u1P)} {(u2P),(u3P)}
__device__ ulonglong2 g_prep[126];

__global__ void ds_prep(const float* __restrict__ W,
                        const float* __restrict__ BETA,
                        const float* __restrict__ alpha,
                        const float* __restrict__ gamma)
{
    __shared__ float ssc[KK];
    const int t = threadIdx.x;
    if (t < KK) { float g = gamma[t]; ssc[t] = g * g * L2E; }
    __syncthreads();

    if (t < KK / 2) {            // epilogue consts for k-pair t = (2t, 2t+1)
        int k0 = 2 * t, k1 = 2 * t + 1;
        float w2[2] = {0.f, 0.f};
        for (int c = 0; c < CC; c++) {
            float a = W[k0 * CC + c], b = W[k1 * CC + c];
            w2[0] += a * a; w2[1] += b * b;
        }
        float hgn0 = -0.5f * ssc[k0], hgn1 = -0.5f * ssc[k1];
        float ap0 = 0.99f / (1.0f + expf(-alpha[k0]));
        float ap1 = 0.99f / (1.0f + expf(-alpha[k1]));
        float c20 = hgn0 * w2[0] + log2f(ap0);
        float c21 = hgn1 * w2[1] + log2f(ap1);
        float u0[MM], u1[MM]; float s0 = 0.f, s1 = 0.f;
        for (int m = 0; m < MM; m++) {
            float b0 = BETA[k0 * MM + m], b1 = BETA[k1 * MM + m];
            u0[m] = b0 * b0; u1[m] = b1 * b1; s0 += u0[m]; s1 += u1[m];
        }
        for (int m = 0; m < MM; m++) { u0[m] /= s0; u1[m] /= s1; }
        int base = 96 + t * 3;
        g_prep[base + 0] = make_ulonglong2(pk(hgn0, hgn1), pk(c20, c21));
        g_prep[base + 1] = make_ulonglong2(pk(u0[0], u1[0]), pk(u0[1], u1[1]));
        g_prep[base + 2] = make_ulonglong2(pk(u0[2], u1[2]), pk(u0[3], u1[3]));
    }

    // weights: thread t handles (half, c) = (t>>4, t&15); needs exactly 32 threads
    {
        int half = t >> 4, c = t & 15;
        int kb = half * 10;
        u64 p01 = pk(ssc[kb+0] * W[(kb+0)*CC + c], ssc[kb+1] * W[(kb+1)*CC + c]);
        u64 p23 = pk(ssc[kb+2] * W[(kb+2)*CC + c], ssc[kb+3] * W[(kb+3)*CC + c]);
        u64 p45 = pk(ssc[kb+4] * W[(kb+4)*CC + c], ssc[kb+5] * W[(kb+5)*CC + c]);
        u64 p67 = pk(ssc[kb+6] * W[(kb+6)*CC + c], ssc[kb+7] * W[(kb+7)*CC + c]);
        u64 p89 = pk(ssc[kb+8] * W[(kb+8)*CC + c], ssc[kb+9] * W[(kb+9)*CC + c]);
        int base = (half * 16 + c) * 3;
        g_prep[base + 0] = make_ulonglong2(p01, p23);
        g_prep[base + 1] = make_ulonglong2(p45, p67);
        g_prep[base + 2] = make_ulonglong2(p89, 0ull);
    }
}

__global__ __launch_bounds__(BLK, 8) void ds_main(
    const float* __restrict__ x,
    float* __restrict__ out)
{
    const int gidx = blockIdx.x * BLK + threadIdx.x;   // point-pair index
    const int b    = gidx >> 17;                       // / PWD
    const int sp   = gidx & (PWD - 1);
    const u64* xb  = (const u64*)x + ((size_t)b * CC << 17) + sp;

    // running products, k-pair lanes, per point (2 points)
    u64 O[2], P0[2], P1[2], P2[2], P3[2];
    #pragma unroll
    for (int p = 0; p < 2; p++) { O[p]=ONEp; P0[p]=ONEp; P1[p]=ONEp; P2[p]=ONEp; P3[p]=ONEp; }
    u64 x2d[2];                 // dup-packed ||x||^2 per point
    u64 x2p = 0ull;             // packed (pt0, pt1) during pass 0

    #pragma unroll
    for (int half = 0; half < 2; half++) {
        // dot pass: A[j][p] = (sc_{k0}<x,W_{k0}>, sc_{k1}<x,W_{k1}>), k0 = half*10+2j
        u64 A[5][2];
        #pragma unroll
        for (int j = 0; j < 5; j++) { A[j][0] = 0ull; A[j][1] = 0ull; }

        #pragma unroll
        for (int c = 0; c < CC; c++) {
            u64 xv = __ldg(xb + ((size_t)c << 17));     // 2 consecutive points
            if (half == 0) x2p = fma2(xv, xv, x2p);
            float xl, xh; upk(xv, xl, xh);
            u64 xd0 = pk(xl, xl), xd1 = pk(xh, xh);

            const int wb = (half * 16 + c) * 3;
            ulonglong2 wA = ldu2(&g_prep[wb + 0]);      // uniform LDG.128 broadcast
            ulonglong2 wB = ldu2(&g_prep[wb + 1]);
            ulonglong2 wC = ldu2(&g_prep[wb + 2]);
            A[0][0] = fma2(xd0, wA.x, A[0][0]);  A[0][1] = fma2(xd1, wA.x, A[0][1]);
            A[1][0] = fma2(xd0, wA.y, A[1][0]);  A[1][1] = fma2(xd1, wA.y, A[1][1]);
            A[2][0] = fma2(xd0, wB.x, A[2][0]);  A[2][1] = fma2(xd1, wB.x, A[2][1]);
            A[3][0] = fma2(xd0, wB.y, A[3][0]);  A[3][1] = fma2(xd1, wB.y, A[3][1]);
            A[4][0] = fma2(xd0, wC.x, A[4][0]);  A[4][1] = fma2(xd1, wC.x, A[4][1]);
        }

        if (half == 0) {
            float a0, a1; upk(x2p, a0, a1);
            x2d[0] = pk(a0, a0); x2d[1] = pk(a1, a1);
        }

        // epilogue over this half's 5 k-pairs
        #pragma unroll
        for (int j = 0; j < 5; j++) {
            const int eb = 96 + (half * 5 + j) * 3;
            ulonglong2 e0 = ldu2(&g_prep[eb + 0]);      // (hgnP, c2P)
            ulonglong2 e1 = ldu2(&g_prep[eb + 1]);      // (u0P, u1P)
            ulonglong2 e2 = ldu2(&g_prep[eb + 2]);      // (u2P, u3P)
            #pragma unroll
            for (int p = 0; p < 2; p++) {
                u64 t = add2(fma2(e0.x, x2d[p], e0.y), A[j][p]);
                float tl, th; upk(t, tl, th);
                u64 s   = pk(ex2f(tl), ex2f(th));
                u64 oms = fma2(s, NEG1p, ONEp);
                O[p]  = mul2(O[p],  oms);
                P0[p] = mul2(P0[p], fma2(e1.x, s, oms));
                P1[p] = mul2(P1[p], fma2(e1.y, s, oms));
                P2[p] = mul2(P2[p], fma2(e2.x, s, oms));
                P3[p] = mul2(P3[p], fma2(e2.y, s, oms));
            }
        }
    }

    // fuse k-pair lanes per point, normalize, store packed point-pairs
    float r0[2], r1[2], r2[2], r3[2], r4[2];
    #pragma unroll
    for (int p = 0; p < 2; p++) {
        float l, h;
        upk(O[p],  l, h); float Os = l * h;
        upk(P0[p], l, h); float f0 = l * h - Os;
        upk(P1[p], l, h); float f1 = l * h - Os;
        upk(P2[p], l, h); float f2 = l * h - Os;
        upk(P3[p], l, h); float f3 = l * h - Os;
        float sum = ((f0 + f1) + (f2 + f3)) + Os;
        float inv = rcpf(sum);
        r0[p] = f0 * inv; r1[p] = f1 * inv; r2[p] = f2 * inv;
        r3[p] = f3 * inv; r4[p] = Os * inv;
    }
    u64* ob = (u64*)out + ((size_t)b * (MM + 1) << 17) + sp;
    ob[(size_t)0 << 17] = pk(r0[0], r0[1]);
    ob[(size_t)1 << 17] = pk(r1[0], r1[1]);
    ob[(size_t)2 << 17] = pk(r2[0], r2[1]);
    ob[(size_t)3 << 17] = pk(r3[0], r3[1]);
    ob[(size_t)4 << 17] = pk(r4[0], r4[1]);
}

extern "C" void kernel_launch(void* const* d_in, const int* in_sizes, int n_in,
                              void* d_out, int out_size)
{
    const float* x     = (const float*)d_in[0];
    const float* Wp    = (const float*)d_in[1];
    const float* BETA  = (const float*)d_in[2];
    const float* alpha = (const float*)d_in[3];
    const float* gamma = (const float*)d_in[4];
    float* out = (float*)d_out;

    ds_prep<<<1, 32>>>(Wp, BETA, alpha, gamma);
    ds_main<<<NTHR / BLK, BLK>>>(x, out);
}

// round 12
// speedup vs baseline: 1.5355x; 1.5355x over previous
#include <cuda_runtime.h>

// Dempster-Shafer evidential layer — single kernel.
// Per-block preamble computes all uniform operands (k-pair packed, NOT
// duplicated) into 2KB shared; main loop reads them as broadcast LDS.128
// (N=1, no crossbar penalty). k-pairs in f32x2 lanes; 2 points/thread;
// K split into halves of 10 prototypes to bound live registers (~72).
//
// s_k = 2^( hgn_k*||x||^2 + <x, sc_k*W_k> + c2_k ),  sc_k = gamma_k^2*log2e,
// hgn_k = -0.5*sc_k,  c2_k = hgn_k*||W_k||^2 + log2(alphap_k)
// Q_m = prod_k (U[k][m]*s_k + (1-s_k)),  O = prod_k (1-s_k)
// out = normalize([Q_m - O, O])

#define CC   16
#define KK   20
#define MM   4
#define HWD  (64*64*64)
#define PWD  (HWD/2)           // 131072 point-pairs per volume
#define NTHR (2*PWD)           // 262144 threads
#define BLK  128

typedef unsigned long long u64;

__device__ __forceinline__ u64 fma2(u64 a, u64 b, u64 c) {
    u64 d; asm("fma.rn.f32x2 %0, %1, %2, %3;" : "=l"(d) : "l"(a), "l"(b), "l"(c)); return d;
}
__device__ __forceinline__ u64 mul2(u64 a, u64 b) {
    u64 d; asm("mul.rn.f32x2 %0, %1, %2;" : "=l"(d) : "l"(a), "l"(b)); return d;
}
__device__ __forceinline__ u64 add2(u64 a, u64 b) {
    u64 d; asm("add.rn.f32x2 %0, %1, %2;" : "=l"(d) : "l"(a), "l"(b)); return d;
}
__device__ __forceinline__ u64 pk(float lo, float hi) {
    u64 r; asm("mov.b64 %0, {%1,%2};" : "=l"(r) : "f"(lo), "f"(hi)); return r;
}
__device__ __forceinline__ void upk(u64 v, float& lo, float& hi) {
    asm("mov.b64 {%0,%1}, %2;" : "=f"(lo), "=f"(hi) : "l"(v));
}
__device__ __forceinline__ float ex2f(float x) {
    float r; asm("ex2.approx.f32 %0, %1;" : "=f"(r) : "f"(x)); return r;
}
__device__ __forceinline__ float rcpf(float x) {
    float r; asm("rcp.approx.f32 %0, %1;" : "=f"(r) : "f"(x)); return r;
}

#define ONEp  0x3F8000003F800000ull
#define NEG1p 0xBF800000BF800000ull
#define L2E   1.4426950408889634f

// Shared layout (ulonglong2 units):
//  [0..95]   weights: (half,c) -> 3 vecs: {(w01),(w23)} {(w45),(w67)} {(w89),pad}
//            wAB = pk(sc[kb+A]*W[kb+A][c], sc[kb+B]*W[kb+B][c]), kb = half*10
//  [96..125] epilogue: kpair jp -> 3 vecs: {(hgnP),(c2P)} {(u0P),(u1P)} {(u2P),(u3P)}

__global__ __launch_bounds__(BLK, 7) void ds_main(
    const float* __restrict__ x,
    const float* __restrict__ W,
    const float* __restrict__ BETA,
    const float* __restrict__ alpha,
    const float* __restrict__ gamma,
    float* __restrict__ out)
{
    __shared__ ulonglong2 sP[126];
    __shared__ float ssc[KK];

    const int tid = threadIdx.x;

    // ---- per-block constant preamble (~1% of block runtime) ----
    if (tid < KK) { float g = gamma[tid]; ssc[tid] = g * g * L2E; }
    __syncthreads();

    if (tid < KK / 2) {          // epilogue consts for k-pair (2t, 2t+1)
        int k0 = 2 * tid, k1 = 2 * tid + 1;
        float w2a = 0.f, w2b = 0.f;
        #pragma unroll
        for (int c = 0; c < CC; c++) {
            float a = W[k0 * CC + c], b = W[k1 * CC + c];
            w2a = fmaf(a, a, w2a); w2b = fmaf(b, b, w2b);
        }
        float hgn0 = -0.5f * ssc[k0], hgn1 = -0.5f * ssc[k1];
        float ap0 = 0.99f / (1.0f + __expf(-alpha[k0]));
        float ap1 = 0.99f / (1.0f + __expf(-alpha[k1]));
        float c20 = hgn0 * w2a + __log2f(ap0);
        float c21 = hgn1 * w2b + __log2f(ap1);
        float u0[MM], u1[MM]; float s0 = 0.f, s1 = 0.f;
        #pragma unroll
        for (int m = 0; m < MM; m++) {
            float b0 = BETA[k0 * MM + m], b1 = BETA[k1 * MM + m];
            u0[m] = b0 * b0; u1[m] = b1 * b1; s0 += u0[m]; s1 += u1[m];
        }
        float i0 = __fdividef(1.f, s0), i1 = __fdividef(1.f, s1);
        int base = 96 + tid * 3;
        sP[base + 0] = make_ulonglong2(pk(hgn0, hgn1), pk(c20, c21));
        sP[base + 1] = make_ulonglong2(pk(u0[0]*i0, u1[0]*i1), pk(u0[1]*i0, u1[1]*i1));
        sP[base + 2] = make_ulonglong2(pk(u0[2]*i0, u1[2]*i1), pk(u0[3]*i0, u1[3]*i1));
    }
    if (tid < 32) {              // weights: (half, c) = (tid>>4, tid&15)
        int half = tid >> 4, c = tid & 15;
        int kb = half * 10;
        u64 p01 = pk(ssc[kb+0] * W[(kb+0)*CC + c], ssc[kb+1] * W[(kb+1)*CC + c]);
        u64 p23 = pk(ssc[kb+2] * W[(kb+2)*CC + c], ssc[kb+3] * W[(kb+3)*CC + c]);
        u64 p45 = pk(ssc[kb+4] * W[(kb+4)*CC + c], ssc[kb+5] * W[(kb+5)*CC + c]);
        u64 p67 = pk(ssc[kb+6] * W[(kb+6)*CC + c], ssc[kb+7] * W[(kb+7)*CC + c]);
        u64 p89 = pk(ssc[kb+8] * W[(kb+8)*CC + c], ssc[kb+9] * W[(kb+9)*CC + c]);
        int base = (half * 16 + c) * 3;
        sP[base + 0] = make_ulonglong2(p01, p23);
        sP[base + 1] = make_ulonglong2(p45, p67);
        sP[base + 2] = make_ulonglong2(p89, 0ull);
    }
    __syncthreads();

    // ---- main per-thread work: 1 point-pair ----
    const int gidx = blockIdx.x * BLK + tid;           // point-pair index
    const int b    = gidx >> 17;                       // / PWD
    const int sp   = gidx & (PWD - 1);
    const u64* xb  = (const u64*)x + ((size_t)b * CC << 17) + sp;

    u64 O[2], P0[2], P1[2], P2[2], P3[2];
    #pragma unroll
    for (int p = 0; p < 2; p++) { O[p]=ONEp; P0[p]=ONEp; P1[p]=ONEp; P2[p]=ONEp; P3[p]=ONEp; }
    u64 x2d[2];
    u64 x2p = 0ull;

    #pragma unroll
    for (int half = 0; half < 2; half++) {
        u64 A[5][2];
        #pragma unroll
        for (int j = 0; j < 5; j++) { A[j][0] = 0ull; A[j][1] = 0ull; }

        #pragma unroll
        for (int c = 0; c < CC; c++) {
            u64 xv = __ldg(xb + ((size_t)c << 17));     // 2 consecutive points
            if (half == 0) x2p = fma2(xv, xv, x2p);
            float xl, xh; upk(xv, xl, xh);
            u64 xd0 = pk(xl, xl), xd1 = pk(xh, xh);

            const int wb = (half * 16 + c) * 3;
            ulonglong2 wA = sP[wb + 0];                 // broadcast LDS.128
            ulonglong2 wB = sP[wb + 1];
            ulonglong2 wC = sP[wb + 2];
            A[0][0] = fma2(xd0, wA.x, A[0][0]);  A[0][1] = fma2(xd1, wA.x, A[0][1]);
            A[1][0] = fma2(xd0, wA.y, A[1][0]);  A[1][1] = fma2(xd1, wA.y, A[1][1]);
            A[2][0] = fma2(xd0, wB.x, A[2][0]);  A[2][1] = fma2(xd1, wB.x, A[2][1]);
            A[3][0] = fma2(xd0, wB.y, A[3][0]);  A[3][1] = fma2(xd1, wB.y, A[3][1]);
            A[4][0] = fma2(xd0, wC.x, A[4][0]);  A[4][1] = fma2(xd1, wC.x, A[4][1]);
        }

        if (half == 0) {
            float a0, a1; upk(x2p, a0, a1);
            x2d[0] = pk(a0, a0); x2d[1] = pk(a1, a1);
        }

        #pragma unroll
        for (int j = 0; j < 5; j++) {
            const int eb = 96 + (half * 5 + j) * 3;
            ulonglong2 e0 = sP[eb + 0];    // (hgnP, c2P)
            ulonglong2 e1 = sP[eb + 1];    // (u0P, u1P)
            ulonglong2 e2 = sP[eb + 2];    // (u2P, u3P)
            #pragma unroll
            for (int p = 0; p < 2; p++) {
                u64 t = add2(fma2(e0.x, x2d[p], e0.y), A[j][p]);
                float tl, th; upk(t, tl, th);
                u64 s   = pk(ex2f(tl), ex2f(th));
                u64 oms = fma2(s, NEG1p, ONEp);
                O[p]  = mul2(O[p],  oms);
                P0[p] = mul2(P0[p], fma2(e1.x, s, oms));
                P1[p] = mul2(P1[p], fma2(e1.y, s, oms));
                P2[p] = mul2(P2[p], fma2(e2.x, s, oms));
                P3[p] = mul2(P3[p], fma2(e2.y, s, oms));
            }
        }
    }

    // fuse k-pair lanes per point, normalize, store packed point-pairs
    float r0[2], r1[2], r2[2], r3[2], r4[2];
    #pragma unroll
    for (int p = 0; p < 2; p++) {
        float l, h;
        upk(O[p],  l, h); float Os = l * h;
        upk(P0[p], l, h); float f0 = l * h - Os;
        upk(P1[p], l, h); float f1 = l * h - Os;
        upk(P2[p], l, h); float f2 = l * h - Os;
        upk(P3[p], l, h); float f3 = l * h - Os;
        float sum = ((f0 + f1) + (f2 + f3)) + Os;
        float inv = rcpf(sum);
        r0[p] = f0 * inv; r1[p] = f1 * inv; r2[p] = f2 * inv;
        r3[p] = f3 * inv; r4[p] = Os * inv;
    }
    u64* ob = (u64*)out + ((size_t)b * (MM + 1) << 17) + sp;
    ob[(size_t)0 << 17] = pk(r0[0], r0[1]);
    ob[(size_t)1 << 17] = pk(r1[0], r1[1]);
    ob[(size_t)2 << 17] = pk(r2[0], r2[1]);
    ob[(size_t)3 << 17] = pk(r3[0], r3[1]);
    ob[(size_t)4 << 17] = pk(r4[0], r4[1]);
}

extern "C" void kernel_launch(void* const* d_in, const int* in_sizes, int n_in,
                              void* d_out, int out_size)
{
    const float* x     = (const float*)d_in[0];
    const float* Wp    = (const float*)d_in[1];
    const float* BETA  = (const float*)d_in[2];
    const float* alpha = (const float*)d_in[3];
    const float* gamma = (const float*)d_in[4];
    float* out = (float*)d_out;

    ds_main<<<NTHR / BLK, BLK>>>(x, Wp, BETA, alpha, gamma, out);
}

// round 13
// speedup vs baseline: 1.6652x; 1.0845x over previous
#include <cuda_runtime.h>

// Dempster-Shafer evidential layer — R6 configuration (best known):
// prep kernel -> __device__ buffer -> cudaMemcpyToSymbolAsync -> __constant__,
// main kernel reads uniform operands via LDC (dedicated constant port).
// k-pairs in f32x2 lanes; 2 points/thread; K split into halves of 10.
// R9 deltas: __launch_bounds__(128,8) (64-reg cap, 32 warps/SM) and dot
// accumulators initialized with folded c2 constants (epilogue add2 removed).
//
// s_k = 2^( hgn_k*||x||^2 + <x, sc_k*W_k> + c2_k ),  sc_k = gamma_k^2*log2e,
// hgn_k = -0.5*sc_k,  c2_k = hgn_k*||W_k||^2 + log2(alphap_k)
// Q_m = prod_k (U[k][m]*s_k + (1-s_k)),  O = prod_k (1-s_k)
// out = normalize([Q_m - O, O])

#define CC   16
#define KK   20
#define MM   4
#define HWD  (64*64*64)
#define PWD  (HWD/2)           // 131072 point-pairs per volume
#define NTHR (2*PWD)           // 262144 threads
#define BLK  128

typedef unsigned long long u64;

__device__ __forceinline__ u64 fma2(u64 a, u64 b, u64 c) {
    u64 d; asm("fma.rn.f32x2 %0, %1, %2, %3;" : "=l"(d) : "l"(a), "l"(b), "l"(c)); return d;
}
__device__ __forceinline__ u64 mul2(u64 a, u64 b) {
    u64 d; asm("mul.rn.f32x2 %0, %1, %2;" : "=l"(d) : "l"(a), "l"(b)); return d;
}
__device__ __forceinline__ u64 add2(u64 a, u64 b) {
    u64 d; asm("add.rn.f32x2 %0, %1, %2;" : "=l"(d) : "l"(a), "l"(b)); return d;
}
__device__ __forceinline__ u64 pk(float lo, float hi) {
    u64 r; asm("mov.b64 %0, {%1,%2};" : "=l"(r) : "f"(lo), "f"(hi)); return r;
}
__device__ __forceinline__ void upk(u64 v, float& lo, float& hi) {
    asm("mov.b64 {%0,%1}, %2;" : "=f"(lo), "=f"(hi) : "l"(v));
}
__device__ __forceinline__ float ex2f(float x) {
    float r; asm("ex2.approx.f32 %0, %1;" : "=f"(r) : "f"(x)); return r;
}
__device__ __forceinline__ float rcpf(float x) {
    float r; asm("rcp.approx.f32 %0, %1;" : "=f"(r) : "f"(x)); return r;
}

#define ONEp  0x3F8000003F800000ull
#define NEG1p 0xBF800000BF800000ull
#define L2E   1.4426950408889634f

// Layout (ulonglong2 units):
//  [0..95]   weights: (half,c) -> 3 vecs: {(w01),(w23)} {(w45),(w67)} {(w89),pad}
//            wAB = pk(sc[kb+A]*W[kb+A][c], sc[kb+B]*W[kb+B][c]), kb = half*10
//  [96..125] epilogue: kpair jp -> 3 vecs: {(hgnP),(c2P)} {(u0P),(u1P)} {(u2P),(u3P)}
__constant__ ulonglong2 cb2[126];
__device__   ulonglong2 g_prep[126];

__global__ void ds_prep(const float* __restrict__ W,
                        const float* __restrict__ BETA,
                        const float* __restrict__ alpha,
                        const float* __restrict__ gamma)
{
    __shared__ float ssc[KK];
    const int t = threadIdx.x;
    if (t < KK) { float g = gamma[t]; ssc[t] = g * g * L2E; }
    __syncthreads();

    if (t < KK / 2) {            // epilogue consts for k-pair t = (2t, 2t+1)
        int k0 = 2 * t, k1 = 2 * t + 1;
        float w2[2] = {0.f, 0.f};
        for (int c = 0; c < CC; c++) {
            float a = W[k0 * CC + c], b = W[k1 * CC + c];
            w2[0] += a * a; w2[1] += b * b;
        }
        float hgn0 = -0.5f * ssc[k0], hgn1 = -0.5f * ssc[k1];
        float ap0 = 0.99f / (1.0f + expf(-alpha[k0]));
        float ap1 = 0.99f / (1.0f + expf(-alpha[k1]));
        float c20 = hgn0 * w2[0] + log2f(ap0);
        float c21 = hgn1 * w2[1] + log2f(ap1);
        float u0[MM], u1[MM]; float s0 = 0.f, s1 = 0.f;
        for (int m = 0; m < MM; m++) {
            float b0 = BETA[k0 * MM + m], b1 = BETA[k1 * MM + m];
            u0[m] = b0 * b0; u1[m] = b1 * b1; s0 += u0[m]; s1 += u1[m];
        }
        for (int m = 0; m < MM; m++) { u0[m] /= s0; u1[m] /= s1; }
        int base = 96 + t * 3;
        g_prep[base + 0] = make_ulonglong2(pk(hgn0, hgn1), pk(c20, c21));
        g_prep[base + 1] = make_ulonglong2(pk(u0[0], u1[0]), pk(u0[1], u1[1]));
        g_prep[base + 2] = make_ulonglong2(pk(u0[2], u1[2]), pk(u0[3], u1[3]));
    }

    // weights: thread t handles (half, c) = (t>>4, t&15); needs exactly 32 threads
    {
        int half = t >> 4, c = t & 15;
        int kb = half * 10;
        u64 p01 = pk(ssc[kb+0] * W[(kb+0)*CC + c], ssc[kb+1] * W[(kb+1)*CC + c]);
        u64 p23 = pk(ssc[kb+2] * W[(kb+2)*CC + c], ssc[kb+3] * W[(kb+3)*CC + c]);
        u64 p45 = pk(ssc[kb+4] * W[(kb+4)*CC + c], ssc[kb+5] * W[(kb+5)*CC + c]);
        u64 p67 = pk(ssc[kb+6] * W[(kb+6)*CC + c], ssc[kb+7] * W[(kb+7)*CC + c]);
        u64 p89 = pk(ssc[kb+8] * W[(kb+8)*CC + c], ssc[kb+9] * W[(kb+9)*CC + c]);
        int base = (half * 16 + c) * 3;
        g_prep[base + 0] = make_ulonglong2(p01, p23);
        g_prep[base + 1] = make_ulonglong2(p45, p67);
        g_prep[base + 2] = make_ulonglong2(p89, 0ull);
    }
}

__global__ __launch_bounds__(BLK, 8) void ds_main(
    const float* __restrict__ x,
    float* __restrict__ out)
{
    const int gidx = blockIdx.x * BLK + threadIdx.x;   // point-pair index
    const int b    = gidx >> 17;                       // / PWD
    const int sp   = gidx & (PWD - 1);
    const u64* xb  = (const u64*)x + ((size_t)b * CC << 17) + sp;

    // running products, k-pair lanes, per point (2 points)
    u64 O[2], P0[2], P1[2], P2[2], P3[2];
    #pragma unroll
    for (int p = 0; p < 2; p++) { O[p]=ONEp; P0[p]=ONEp; P1[p]=ONEp; P2[p]=ONEp; P3[p]=ONEp; }
    u64 x2d[2];                 // dup-packed ||x||^2 per point
    u64 x2p = 0ull;             // packed (pt0, pt1) during pass 0

    #pragma unroll
    for (int half = 0; half < 2; half++) {
        // dot accumulators seeded with the folded constant c2P (saves epilogue add2)
        u64 A[5][2];
        #pragma unroll
        for (int j = 0; j < 5; j++) {
            u64 c2v = cb2[96 + (half * 5 + j) * 3].y;   // (c20, c21) for this k-pair
            A[j][0] = c2v; A[j][1] = c2v;
        }

        #pragma unroll
        for (int c = 0; c < CC; c++) {
            u64 xv = __ldg(xb + ((size_t)c << 17));     // 2 consecutive points
            if (half == 0) x2p = fma2(xv, xv, x2p);
            float xl, xh; upk(xv, xl, xh);
            u64 xd0 = pk(xl, xl), xd1 = pk(xh, xh);

            const int wb = (half * 16 + c) * 3;
            ulonglong2 wA = cb2[wb + 0];                // LDC.128 broadcast
            ulonglong2 wB = cb2[wb + 1];
            ulonglong2 wC = cb2[wb + 2];
            A[0][0] = fma2(xd0, wA.x, A[0][0]);  A[0][1] = fma2(xd1, wA.x, A[0][1]);
            A[1][0] = fma2(xd0, wA.y, A[1][0]);  A[1][1] = fma2(xd1, wA.y, A[1][1]);
            A[2][0] = fma2(xd0, wB.x, A[2][0]);  A[2][1] = fma2(xd1, wB.x, A[2][1]);
            A[3][0] = fma2(xd0, wB.y, A[3][0]);  A[3][1] = fma2(xd1, wB.y, A[3][1]);
            A[4][0] = fma2(xd0, wC.x, A[4][0]);  A[4][1] = fma2(xd1, wC.x, A[4][1]);
        }

        if (half == 0) {
            float a0, a1; upk(x2p, a0, a1);
            x2d[0] = pk(a0, a0); x2d[1] = pk(a1, a1);
        }

        // epilogue over this half's 5 k-pairs
        #pragma unroll
        for (int j = 0; j < 5; j++) {
            const int eb = 96 + (half * 5 + j) * 3;
            u64 hgnP       = cb2[eb + 0].x;  // (hgn0, hgn1)
            ulonglong2 e1  = cb2[eb + 1];    // (u0P, u1P)
            ulonglong2 e2  = cb2[eb + 2];    // (u2P, u3P)
            #pragma unroll
            for (int p = 0; p < 2; p++) {
                u64 t = fma2(hgnP, x2d[p], A[j][p]);    // c2 already folded into A
                float tl, th; upk(t, tl, th);
                u64 s   = pk(ex2f(tl), ex2f(th));
                u64 oms = fma2(s, NEG1p, ONEp);
                O[p]  = mul2(O[p],  oms);
                P0[p] = mul2(P0[p], fma2(e1.x, s, oms));
                P1[p] = mul2(P1[p], fma2(e1.y, s, oms));
                P2[p] = mul2(P2[p], fma2(e2.x, s, oms));
                P3[p] = mul2(P3[p], fma2(e2.y, s, oms));
            }
        }
    }

    // fuse k-pair lanes per point, normalize, store packed point-pairs
    float r0[2], r1[2], r2[2], r3[2], r4[2];
    #pragma unroll
    for (int p = 0; p < 2; p++) {
        float l, h;
        upk(O[p],  l, h); float Os = l * h;
        upk(P0[p], l, h); float f0 = l * h - Os;
        upk(P1[p], l, h); float f1 = l * h - Os;
        upk(P2[p], l, h); float f2 = l * h - Os;
        upk(P3[p], l, h); float f3 = l * h - Os;
        float sum = ((f0 + f1) + (f2 + f3)) + Os;
        float inv = rcpf(sum);
        r0[p] = f0 * inv; r1[p] = f1 * inv; r2[p] = f2 * inv;
        r3[p] = f3 * inv; r4[p] = Os * inv;
    }
    u64* ob = (u64*)out + ((size_t)b * (MM + 1) << 17) + sp;
    ob[(size_t)0 << 17] = pk(r0[0], r0[1]);
    ob[(size_t)1 << 17] = pk(r1[0], r1[1]);
    ob[(size_t)2 << 17] = pk(r2[0], r2[1]);
    ob[(size_t)3 << 17] = pk(r3[0], r3[1]);
    ob[(size_t)4 << 17] = pk(r4[0], r4[1]);
}

extern "C" void kernel_launch(void* const* d_in, const int* in_sizes, int n_in,
                              void* d_out, int out_size)
{
    const float* x     = (const float*)d_in[0];
    const float* Wp    = (const float*)d_in[1];
    const float* BETA  = (const float*)d_in[2];
    const float* alpha = (const float*)d_in[3];
    const float* gamma = (const float*)d_in[4];
    float* out = (float*)d_out;

    ds_prep<<<1, 32>>>(Wp, BETA, alpha, gamma);

    void* src = nullptr;
    cudaGetSymbolAddress(&src, g_prep);
    cudaMemcpyToSymbolAsync(cb2, src, sizeof(ulonglong2) * 126, 0,
                            cudaMemcpyDeviceToDevice, 0);

    ds_main<<<NTHR / BLK, BLK>>>(x, out);
}

// round 17
// speedup vs baseline: 1.8431x; 1.1068x over previous
#include <cuda_runtime.h>

// Dempster-Shafer evidential layer — R6 plumbing (known graph-capturable):
// prep kernel -> __device__ g_prep -> cudaMemcpyToSymbolAsync -> __constant__,
// main kernel reads uniform operands via LDC (dedicated constant port).
// k-pairs in f32x2 lanes; 2 points/thread; K split into halves of 10.
// R11 delta vs R6: dot accumulators seeded with folded c2 constants
// (epilogue add2 removed) at the validated 72-reg / 7-block operating point.
// (Round-16 run was an infra failure; this is the same candidate, unmeasured.)
//
// s_k = 2^( hgn_k*||x||^2 + <x, sc_k*W_k> + c2_k ),  sc_k = gamma_k^2*log2e,
// hgn_k = -0.5*sc_k,  c2_k = hgn_k*||W_k||^2 + log2(alphap_k)
// Q_m = prod_k (U[k][m]*s_k + (1-s_k)),  O = prod_k (1-s_k)
// out = normalize([Q_m - O, O])

#define CC   16
#define KK   20
#define MM   4
#define HWD  (64*64*64)
#define PWD  (HWD/2)           // 131072 point-pairs per volume
#define NTHR (2*PWD)           // 262144 threads
#define BLK  128

typedef unsigned long long u64;

__device__ __forceinline__ u64 fma2(u64 a, u64 b, u64 c) {
    u64 d; asm("fma.rn.f32x2 %0, %1, %2, %3;" : "=l"(d) : "l"(a), "l"(b), "l"(c)); return d;
}
__device__ __forceinline__ u64 mul2(u64 a, u64 b) {
    u64 d; asm("mul.rn.f32x2 %0, %1, %2;" : "=l"(d) : "l"(a), "l"(b)); return d;
}
__device__ __forceinline__ u64 add2(u64 a, u64 b) {
    u64 d; asm("add.rn.f32x2 %0, %1, %2;" : "=l"(d) : "l"(a), "l"(b)); return d;
}
__device__ __forceinline__ u64 pk(float lo, float hi) {
    u64 r; asm("mov.b64 %0, {%1,%2};" : "=l"(r) : "f"(lo), "f"(hi)); return r;
}
__device__ __forceinline__ void upk(u64 v, float& lo, float& hi) {
    asm("mov.b64 {%0,%1}, %2;" : "=f"(lo), "=f"(hi) : "l"(v));
}
__device__ __forceinline__ float ex2f(float x) {
    float r; asm("ex2.approx.f32 %0, %1;" : "=f"(r) : "f"(x)); return r;
}
__device__ __forceinline__ float rcpf(float x) {
    float r; asm("rcp.approx.f32 %0, %1;" : "=f"(r) : "f"(x)); return r;
}

#define ONEp  0x3F8000003F800000ull
#define NEG1p 0xBF800000BF800000ull
#define L2E   1.4426950408889634f

// Layout (ulonglong2 units):
//  [0..95]   weights: (half,c) -> 3 vecs: {(w01),(w23)} {(w45),(w67)} {(w89),pad}
//            wAB = pk(sc[kb+A]*W[kb+A][c], sc[kb+B]*W[kb+B][c]), kb = half*10
//  [96..125] epilogue: kpair jp -> 3 vecs: {(hgnP),(c2P)} {(u0P),(u1P)} {(u2P),(u3P)}
__constant__ ulonglong2 cb2[126];
__device__   ulonglong2 g_prep[126];

__global__ void ds_prep(const float* __restrict__ W,
                        const float* __restrict__ BETA,
                        const float* __restrict__ alpha,
                        const float* __restrict__ gamma)
{
    __shared__ float ssc[KK];
    const int t = threadIdx.x;
    if (t < KK) { float g = gamma[t]; ssc[t] = g * g * L2E; }
    __syncthreads();

    if (t < KK / 2) {            // epilogue consts for k-pair t = (2t, 2t+1)
        int k0 = 2 * t, k1 = 2 * t + 1;
        float w2[2] = {0.f, 0.f};
        for (int c = 0; c < CC; c++) {
            float a = W[k0 * CC + c], b = W[k1 * CC + c];
            w2[0] += a * a; w2[1] += b * b;
        }
        float hgn0 = -0.5f * ssc[k0], hgn1 = -0.5f * ssc[k1];
        float ap0 = 0.99f / (1.0f + expf(-alpha[k0]));
        float ap1 = 0.99f / (1.0f + expf(-alpha[k1]));
        float c20 = hgn0 * w2[0] + log2f(ap0);
        float c21 = hgn1 * w2[1] + log2f(ap1);
        float u0[MM], u1[MM]; float s0 = 0.f, s1 = 0.f;
        for (int m = 0; m < MM; m++) {
            float b0 = BETA[k0 * MM + m], b1 = BETA[k1 * MM + m];
            u0[m] = b0 * b0; u1[m] = b1 * b1; s0 += u0[m]; s1 += u1[m];
        }
        for (int m = 0; m < MM; m++) { u0[m] /= s0; u1[m] /= s1; }
        int base = 96 + t * 3;
        g_prep[base + 0] = make_ulonglong2(pk(hgn0, hgn1), pk(c20, c21));
        g_prep[base + 1] = make_ulonglong2(pk(u0[0], u1[0]), pk(u0[1], u1[1]));
        g_prep[base + 2] = make_ulonglong2(pk(u0[2], u1[2]), pk(u0[3], u1[3]));
    }

    // weights: thread t handles (half, c) = (t>>4, t&15); needs exactly 32 threads
    {
        int half = t >> 4, c = t & 15;
        int kb = half * 10;
        u64 p01 = pk(ssc[kb+0] * W[(kb+0)*CC + c], ssc[kb+1] * W[(kb+1)*CC + c]);
        u64 p23 = pk(ssc[kb+2] * W[(kb+2)*CC + c], ssc[kb+3] * W[(kb+3)*CC + c]);
        u64 p45 = pk(ssc[kb+4] * W[(kb+4)*CC + c], ssc[kb+5] * W[(kb+5)*CC + c]);
        u64 p67 = pk(ssc[kb+6] * W[(kb+6)*CC + c], ssc[kb+7] * W[(kb+7)*CC + c]);
        u64 p89 = pk(ssc[kb+8] * W[(kb+8)*CC + c], ssc[kb+9] * W[(kb+9)*CC + c]);
        int base = (half * 16 + c) * 3;
        g_prep[base + 0] = make_ulonglong2(p01, p23);
        g_prep[base + 1] = make_ulonglong2(p45, p67);
        g_prep[base + 2] = make_ulonglong2(p89, 0ull);
    }
}

__global__ __launch_bounds__(BLK, 7) void ds_main(
    const float* __restrict__ x,
    float* __restrict__ out)
{
    const int gidx = blockIdx.x * BLK + threadIdx.x;   // point-pair index
    const int b    = gidx >> 17;                       // / PWD
    const int sp   = gidx & (PWD - 1);
    const u64* xb  = (const u64*)x + ((size_t)b * CC << 17) + sp;

    // running products, k-pair lanes, per point (2 points)
    u64 O[2], P0[2], P1[2], P2[2], P3[2];
    #pragma unroll
    for (int p = 0; p < 2; p++) { O[p]=ONEp; P0[p]=ONEp; P1[p]=ONEp; P2[p]=ONEp; P3[p]=ONEp; }
    u64 x2d[2];                 // dup-packed ||x||^2 per point
    u64 x2p = 0ull;             // packed (pt0, pt1) during pass 0

    #pragma unroll
    for (int half = 0; half < 2; half++) {
        // dot accumulators seeded with folded c2P (saves epilogue add2)
        u64 A[5][2];
        #pragma unroll
        for (int j = 0; j < 5; j++) {
            u64 c2v = cb2[96 + (half * 5 + j) * 3].y;
            A[j][0] = c2v; A[j][1] = c2v;
        }

        #pragma unroll
        for (int c = 0; c < CC; c++) {
            u64 xv = __ldg(xb + ((size_t)c << 17));     // 2 consecutive points
            if (half == 0) x2p = fma2(xv, xv, x2p);
            float xl, xh; upk(xv, xl, xh);
            u64 xd0 = pk(xl, xl), xd1 = pk(xh, xh);

            const int wb = (half * 16 + c) * 3;
            ulonglong2 wA = cb2[wb + 0];                // LDC.128 broadcast
            ulonglong2 wB = cb2[wb + 1];
            ulonglong2 wC = cb2[wb + 2];
            A[0][0] = fma2(xd0, wA.x, A[0][0]);  A[0][1] = fma2(xd1, wA.x, A[0][1]);
            A[1][0] = fma2(xd0, wA.y, A[1][0]);  A[1][1] = fma2(xd1, wA.y, A[1][1]);
            A[2][0] = fma2(xd0, wB.x, A[2][0]);  A[2][1] = fma2(xd1, wB.x, A[2][1]);
            A[3][0] = fma2(xd0, wB.y, A[3][0]);  A[3][1] = fma2(xd1, wB.y, A[3][1]);
            A[4][0] = fma2(xd0, wC.x, A[4][0]);  A[4][1] = fma2(xd1, wC.x, A[4][1]);
        }

        if (half == 0) {
            float a0, a1; upk(x2p, a0, a1);
            x2d[0] = pk(a0, a0); x2d[1] = pk(a1, a1);
        }

        // epilogue over this half's 5 k-pairs
        #pragma unroll
        for (int j = 0; j < 5; j++) {
            const int eb = 96 + (half * 5 + j) * 3;
            u64 hgnP      = cb2[eb + 0].x;   // (hgn0, hgn1)
            ulonglong2 e1 = cb2[eb + 1];     // (u0P, u1P)
            ulonglong2 e2 = cb2[eb + 2];     // (u2P, u3P)
            #pragma unroll
            for (int p = 0; p < 2; p++) {
                u64 t = fma2(hgnP, x2d[p], A[j][p]);    // c2 folded into A
                float tl, th; upk(t, tl, th);
                u64 s   = pk(ex2f(tl), ex2f(th));
                u64 oms = fma2(s, NEG1p, ONEp);
                O[p]  = mul2(O[p],  oms);
                P0[p] = mul2(P0[p], fma2(e1.x, s, oms));
                P1[p] = mul2(P1[p], fma2(e1.y, s, oms));
                P2[p] = mul2(P2[p], fma2(e2.x, s, oms));
                P3[p] = mul2(P3[p], fma2(e2.y, s, oms));
            }
        }
    }

    // fuse k-pair lanes per point, normalize, store packed point-pairs
    float r0[2], r1[2], r2[2], r3[2], r4[2];
    #pragma unroll
    for (int p = 0; p < 2; p++) {
        float l, h;
        upk(O[p],  l, h); float Os = l * h;
        upk(P0[p], l, h); float f0 = l * h - Os;
        upk(P1[p], l, h); float f1 = l * h - Os;
        upk(P2[p], l, h); float f2 = l * h - Os;
        upk(P3[p], l, h); float f3 = l * h - Os;
        float sum = ((f0 + f1) + (f2 + f3)) + Os;
        float inv = rcpf(sum);
        r0[p] = f0 * inv; r1[p] = f1 * inv; r2[p] = f2 * inv;
        r3[p] = f3 * inv; r4[p] = Os * inv;
    }
    u64* ob = (u64*)out + ((size_t)b * (MM + 1) << 17) + sp;
    ob[(size_t)0 << 17] = pk(r0[0], r0[1]);
    ob[(size_t)1 << 17] = pk(r1[0], r1[1]);
    ob[(size_t)2 << 17] = pk(r2[0], r2[1]);
    ob[(size_t)3 << 17] = pk(r3[0], r3[1]);
    ob[(size_t)4 << 17] = pk(r4[0], r4[1]);
}

extern "C" void kernel_launch(void* const* d_in, const int* in_sizes, int n_in,
                              void* d_out, int out_size)
{
    const float* x     = (const float*)d_in[0];
    const float* Wp    = (const float*)d_in[1];
    const float* BETA  = (const float*)d_in[2];
    const float* alpha = (const float*)d_in[3];
    const float* gamma = (const float*)d_in[4];
    float* out = (float*)d_out;

    ds_prep<<<1, 32>>>(Wp, BETA, alpha, gamma);

    void* src = nullptr;
    cudaGetSymbolAddress(&src, g_prep);
    cudaMemcpyToSymbolAsync(cb2, src, sizeof(ulonglong2) * 126, 0,
                            cudaMemcpyDeviceToDevice, 0);

    ds_main<<<NTHR / BLK, BLK>>>(x, out);
}